// round 7
// baseline (speedup 1.0000x reference)
#include <cuda_runtime.h>
#include <stdint.h>

#define D 128
#define MAX_NODES 100000
#define NSM 148            // persistent CTAs; <= SM count on B300/GB300
#define TILE_ROWS 64
#define MAX_TILES 8192

// 51.2 MB scratch for y = x_out @ W0
__device__ float g_y[MAX_NODES * D];
__device__ int   g_bad;                 // nonzero -> edge_index is int32
__device__ int   g_flags[MAX_TILES];    // per-row-tile ready flags

// ---------------------------------------------------------------------------
// helpers
// ---------------------------------------------------------------------------
__device__ __forceinline__ void ldg_el32B(const float* p, float4& lo, float4& hi) {
    unsigned long long x0, x1, x2, x3;
    asm volatile("ld.global.L2::evict_last.v4.b64 {%0,%1,%2,%3}, [%4];"
                 : "=l"(x0), "=l"(x1), "=l"(x2), "=l"(x3) : "l"(p));
    lo.x = __uint_as_float((unsigned)x0); lo.y = __uint_as_float((unsigned)(x0 >> 32));
    lo.z = __uint_as_float((unsigned)x1); lo.w = __uint_as_float((unsigned)(x1 >> 32));
    hi.x = __uint_as_float((unsigned)x2); hi.y = __uint_as_float((unsigned)(x2 >> 32));
    hi.z = __uint_as_float((unsigned)x3); hi.w = __uint_as_float((unsigned)(x3 >> 32));
}
__device__ __forceinline__ void stg_el32B(float* p, unsigned long long x0,
                                          unsigned long long x1,
                                          unsigned long long x2,
                                          unsigned long long x3) {
    asm volatile("st.global.L2::evict_last.v4.b64 [%0], {%1,%2,%3,%4};"
                 :: "l"(p), "l"(x0), "l"(x1), "l"(x2), "l"(x3) : "memory");
}
__device__ __forceinline__ void cp_async4(uint32_t smem_addr, const float* gptr) {
    asm volatile("cp.async.ca.shared.global [%0], [%1], 4;"
                 :: "r"(smem_addr), "l"(gptr));
}

// ---------------------------------------------------------------------------
// Kernel 0: zero flags + detect index dtype (runs first every replay)
// ---------------------------------------------------------------------------
__global__ void init_k(const unsigned int* __restrict__ ei_raw, int nwords)
{
    int gt = blockIdx.x * blockDim.x + threadIdx.x;
    for (int i = gt; i < MAX_TILES; i += gridDim.x * blockDim.x)
        g_flags[i] = 0;

    if (blockIdx.x == 0) {
        __shared__ int bad;
        if (threadIdx.x == 0) bad = 0;
        __syncthreads();
        int limit = 1024;
        if (limit > nwords) limit = nwords & ~1;
        for (int i = threadIdx.x; i * 2 + 1 < limit; i += blockDim.x)
            if (ei_raw[i * 2 + 1] != 0u) atomicOr(&bad, 1);
        __syncthreads();
        if (threadIdx.x == 0) g_bad = bad;
    }
}

// ---------------------------------------------------------------------------
// Fused persistent kernel: warps 0-15 GEMM producer, warps 16-31 edge consumer
// smem: Ws[128*128] | As[2][128*65]
// ---------------------------------------------------------------------------
#define AS_STRIDE 65
#define SMEM_FLOATS (D * D + 2 * D * AS_STRIDE)

__global__ void __launch_bounds__(1024, 1) fused_k(
    const float* __restrict__ x_out,
    const float* __restrict__ W,
    const float* __restrict__ x_in,
    const void*  __restrict__ ei,
    float*       __restrict__ out,
    int n, int E)
{
    extern __shared__ float smem[];
    float* Ws = smem;                 // [k*128 + c]
    float* As = smem + D * D;         // two buffers of [k*65 + r]

    const int tid = threadIdx.x;
    const int bid = blockIdx.x;
    const int ntiles = (n + TILE_ROWS - 1) / TILE_ROWS;

    // cooperative W load (all 1024 threads)
    for (int i = tid; i < (D * D) / 4; i += 1024)
        ((float4*)Ws)[i] = ((const float4*)W)[i];

    if (tid < 512) {
        // ---- prologue: stage first A tile into buffer 0 via cp.async ----
        int t0 = bid;
        if (t0 < ntiles) {
            int r = (tid >> 7);              // 0..3
            int k = tid & 127;
            uint32_t as_base;
            asm("{ .reg .u64 tmp; cvta.to.shared.u64 tmp, %1; cvt.u32.u64 %0, tmp; }"
                : "=r"(as_base) : "l"(As));
            #pragma unroll
            for (int p = 0; p < 16; p++) {
                int rr = p * 4 + r;
                int grow = t0 * TILE_ROWS + rr;
                if (grow >= n) grow = n - 1;
                cp_async4(as_base + (uint32_t)(k * AS_STRIDE + rr) * 4,
                          &x_out[(size_t)grow * D + k]);
            }
            asm volatile("cp.async.commit_group;");
        }
    }
    __syncthreads();   // W ready; roles diverge from here (no more CTA-wide syncs)

    if (tid < 512) {
        // ================= GEMM producer =================
        const int lane = tid & 31;
        const int w    = tid >> 5;        // 0..15 -> cols w*8 .. w*8+7
        const int rS   = tid >> 7;        // staging row sub-index
        const int kS   = tid & 127;       // staging k
        uint32_t as_base;
        asm("{ .reg .u64 tmp; cvta.to.shared.u64 tmp, %1; cvt.u32.u64 %0, tmp; }"
            : "=r"(as_base) : "l"(As));

        int buf = 0;
        for (int t = bid; t < ntiles; t += NSM) {
            // stage next tile into other buffer
            bool has_next = (t + NSM) < ntiles;
            if (has_next) {
                int tn = t + NSM;
                uint32_t dstb = as_base + (uint32_t)((buf ^ 1) * D * AS_STRIDE) * 4;
                #pragma unroll
                for (int p = 0; p < 16; p++) {
                    int rr = p * 4 + rS;
                    int grow = tn * TILE_ROWS + rr;
                    if (grow >= n) grow = n - 1;
                    cp_async4(dstb + (uint32_t)(kS * AS_STRIDE + rr) * 4,
                              &x_out[(size_t)grow * D + kS]);
                }
                asm volatile("cp.async.commit_group;");
                asm volatile("cp.async.wait_group 1;");
            } else {
                asm volatile("cp.async.wait_group 0;");
            }
            asm volatile("bar.sync 1, 512;");   // current buffer fully staged

            const float* A = As + buf * D * AS_STRIDE;
            unsigned long long acc[8];
            #pragma unroll
            for (int j = 0; j < 8; j++) acc[j] = 0ull;

            #pragma unroll 8
            for (int kk = 0; kk < D; kk++) {
                float a0 = A[kk * AS_STRIDE + lane];
                float a1 = A[kk * AS_STRIDE + lane + 32];
                unsigned long long aa0, aa1;
                asm("mov.b64 %0, {%1, %1};" : "=l"(aa0) : "r"(__float_as_uint(a0)));
                asm("mov.b64 %0, {%1, %1};" : "=l"(aa1) : "r"(__float_as_uint(a1)));
                const ulonglong2* wp = reinterpret_cast<const ulonglong2*>(&Ws[kk * D + w * 8]);
                ulonglong2 u0 = wp[0];
                ulonglong2 u1 = wp[1];
                asm("fma.rn.f32x2 %0, %1, %2, %0;" : "+l"(acc[0]) : "l"(aa0), "l"(u0.x));
                asm("fma.rn.f32x2 %0, %1, %2, %0;" : "+l"(acc[1]) : "l"(aa0), "l"(u0.y));
                asm("fma.rn.f32x2 %0, %1, %2, %0;" : "+l"(acc[2]) : "l"(aa0), "l"(u1.x));
                asm("fma.rn.f32x2 %0, %1, %2, %0;" : "+l"(acc[3]) : "l"(aa0), "l"(u1.y));
                asm("fma.rn.f32x2 %0, %1, %2, %0;" : "+l"(acc[4]) : "l"(aa1), "l"(u0.x));
                asm("fma.rn.f32x2 %0, %1, %2, %0;" : "+l"(acc[5]) : "l"(aa1), "l"(u0.y));
                asm("fma.rn.f32x2 %0, %1, %2, %0;" : "+l"(acc[6]) : "l"(aa1), "l"(u1.x));
                asm("fma.rn.f32x2 %0, %1, %2, %0;" : "+l"(acc[7]) : "l"(aa1), "l"(u1.y));
            }

            int gr0 = t * TILE_ROWS + lane;
            int gr1 = gr0 + 32;
            if (gr0 < n)
                stg_el32B(g_y + (size_t)gr0 * D + w * 8, acc[0], acc[1], acc[2], acc[3]);
            if (gr1 < n)
                stg_el32B(g_y + (size_t)gr1 * D + w * 8, acc[4], acc[5], acc[6], acc[7]);

            asm volatile("bar.sync 1, 512;");   // all stores issued (also guards buf reuse)
            if (tid == 0) {
                int one = 1;
                asm volatile("st.global.release.gpu.b32 [%0], %1;"
                             :: "l"(&g_flags[t]), "r"(one) : "memory");
            }
            buf ^= 1;
        }
    } else {
        // ================= edge consumer =================
        const int et   = tid - 512;
        const int wE   = et >> 5;          // 0..15
        const int lane = et & 31;
        const int half = lane >> 4;
        const int sub  = lane & 15;
        const int bad  = g_bad;

        long long chunk = ((long long)E + NSM - 1) / NSM;
        long long eBeg = (long long)bid * chunk;
        long long eEnd = eBeg + chunk;
        if (eEnd > E) eEnd = E;

        for (long long e = eBeg + wE * 2 + half; e < eEnd; e += 32) {
            long long s, d;
            if (bad) {
                const int* p = (const int*)ei;
                s = __ldcs(&p[e]);
                d = __ldcs(&p[(long long)E + e]);
            } else {
                const long long* p = (const long long*)ei;
                s = __ldcs(&p[e]);
                d = __ldcs(&p[(long long)E + e]);
            }

            // wait for producer tile containing row s
            const int* fp = &g_flags[(int)(s >> 6)];
            unsigned f;
            while (true) {
                asm volatile("ld.global.acquire.gpu.b32 %0, [%1];" : "=r"(f) : "l"(fp));
                if (f) break;
                __nanosleep(64);
            }

            float4 a0, a1, b0, b1;
            ldg_el32B(g_y  + s * D + sub * 8, a0, a1);
            ldg_el32B(x_in + d * D + sub * 8, b0, b1);

            float v = a0.x * b0.x + a0.y * b0.y + a0.z * b0.z + a0.w * b0.w
                    + a1.x * b1.x + a1.y * b1.y + a1.z * b1.z + a1.w * b1.w;

            #pragma unroll
            for (int o = 8; o > 0; o >>= 1)
                v += __shfl_xor_sync(0xFFFFFFFFu, v, o);

            if (sub == 0)
                __stcs(&out[e], 1.0f / (1.0f + __expf(-v)));
        }
    }
}

// ---------------------------------------------------------------------------
// Launch
// ---------------------------------------------------------------------------
extern "C" void kernel_launch(void* const* d_in, const int* in_sizes, int n_in,
                              void* d_out, int out_size)
{
    int i_xin = 0, i_xout = 1, i_ei = 2, i_w = 3;

    if (n_in == 4) {
        int w_idx = -1, ei_idx = -1;
        for (int i = 0; i < 4; i++)
            if (in_sizes[i] == D * D) w_idx = i;
        int idx[3], c = 0;
        for (int i = 0; i < 4; i++) if (i != w_idx) idx[c++] = i;
        if (w_idx >= 0 && c == 3) {
            if (in_sizes[idx[0]] == in_sizes[idx[1]])      { i_xin = idx[0]; i_xout = idx[1]; ei_idx = idx[2]; }
            else if (in_sizes[idx[0]] == in_sizes[idx[2]]) { i_xin = idx[0]; i_xout = idx[2]; ei_idx = idx[1]; }
            else                                            { i_xin = idx[1]; i_xout = idx[2]; ei_idx = idx[0]; }
            i_w = w_idx; i_ei = ei_idx;
        }
    }

    const float* x_in  = (const float*)d_in[i_xin];
    const float* x_out = (const float*)d_in[i_xout];
    const void*  ei    = d_in[i_ei];
    const float* W     = (const float*)d_in[i_w];
    float*       out   = (float*)d_out;

    int n = in_sizes[i_xin] / D;
    if (n > MAX_NODES) n = MAX_NODES;
    int E = in_sizes[i_ei] / 2;

    init_k<<<16, 256>>>((const unsigned int*)ei, in_sizes[i_ei] * 2);

    static int smem_set = 0;
    size_t smem_bytes = (size_t)SMEM_FLOATS * sizeof(float);
    if (!smem_set) {
        cudaFuncSetAttribute(fused_k, cudaFuncAttributeMaxDynamicSharedMemorySize,
                             (int)smem_bytes);
        smem_set = 1;
    }
    fused_k<<<NSM, 1024, smem_bytes>>>(x_out, W, x_in, ei, out, n, E);
}

// round 8
// speedup vs baseline: 2.2988x; 2.2988x over previous
#include <cuda_runtime.h>
#include <stdint.h>

#define D 128
#define MAX_NODES 100000
#define NSM 148
#define GBM 128                 // GEMM tile rows
#define AST 129                 // A smem stride (odd -> conflict-free)
#define ASZ (D * AST)           // floats per A buffer

// 51.2 MB scratch for y = x_out @ W0
__device__ float g_y[MAX_NODES * D];
__device__ int   g_bad;         // nonzero -> edge_index is int32

// ---------------------------------------------------------------------------
// helpers
// ---------------------------------------------------------------------------
__device__ __forceinline__ void ldg_el32B(const float* p, float4& lo, float4& hi) {
    unsigned long long x0, x1, x2, x3;
    asm volatile("ld.global.nc.L2::evict_last.v4.b64 {%0,%1,%2,%3}, [%4];"
                 : "=l"(x0), "=l"(x1), "=l"(x2), "=l"(x3) : "l"(p));
    lo.x = __uint_as_float((unsigned)x0); lo.y = __uint_as_float((unsigned)(x0 >> 32));
    lo.z = __uint_as_float((unsigned)x1); lo.w = __uint_as_float((unsigned)(x1 >> 32));
    hi.x = __uint_as_float((unsigned)x2); hi.y = __uint_as_float((unsigned)(x2 >> 32));
    hi.z = __uint_as_float((unsigned)x3); hi.w = __uint_as_float((unsigned)(x3 >> 32));
}
__device__ __forceinline__ void stg_el32B(float* p, unsigned long long x0,
                                          unsigned long long x1,
                                          unsigned long long x2,
                                          unsigned long long x3) {
    asm volatile("st.global.L2::evict_last.v4.b64 [%0], {%1,%2,%3,%4};"
                 :: "l"(p), "l"(x0), "l"(x1), "l"(x2), "l"(x3) : "memory");
}
__device__ __forceinline__ void cp_async4(uint32_t smem_addr, const float* gptr) {
    asm volatile("cp.async.ca.shared.global [%0], [%1], 4;"
                 :: "r"(smem_addr), "l"(gptr));
}

// ---------------------------------------------------------------------------
// Persistent GEMM: y = x_out @ W0.  148 CTAs x 512 threads.
// W resident in smem for the whole kernel; A tiles (128x128) double-buffered
// via cp.async. Thread computes 2 rows x 16 cols as 16 packed f32x2 accs.
// ---------------------------------------------------------------------------
__global__ void __launch_bounds__(512, 1) gemm_xout_w(
    const float* __restrict__ x_out,
    const float* __restrict__ W,   // [D*D] row-major W[k*D + c]
    int n)
{
    extern __shared__ float smem[];
    float* Ws = smem;              // [k*128 + c], 64 KB
    float* As = smem + D * D;      // 2 buffers of [k*129 + r]

    const int tid    = threadIdx.x;
    const int bid    = blockIdx.x;
    const int ntiles = (n + GBM - 1) / GBM;

    // load W once (coalesced float4)
    #pragma unroll
    for (int i = tid; i < (D * D) / 4; i += 512)
        ((float4*)Ws)[i] = ((const float4*)W)[i];

    uint32_t as_base;
    asm("{ .reg .u64 t; cvta.to.shared.u64 t, %1; cvt.u32.u64 %0, t; }"
        : "=r"(as_base) : "l"(As));

    const int kS = tid & 127;      // staging: fixed k
    const int rS = tid >> 7;       // staging: row sub-index 0..3

    // prologue: stage tile bid into buffer 0
    if (bid < ntiles) {
        #pragma unroll
        for (int p = 0; p < 32; p++) {
            int rr = p * 4 + rS;
            int grow = bid * GBM + rr;
            if (grow >= n) grow = n - 1;
            cp_async4(as_base + (uint32_t)(kS * AST + rr) * 4,
                      &x_out[(size_t)grow * D + kS]);
        }
        asm volatile("cp.async.commit_group;");
    }

    const int r0 = tid & 63;       // rows r0, r0+64
    const int cg = tid >> 6;       // cols cg*16..+15

    int buf = 0;
    for (int t = bid; t < ntiles; t += NSM) {
        bool has_next = (t + NSM) < ntiles;
        if (has_next) {
            int tn = t + NSM;
            uint32_t dstb = as_base + (uint32_t)((buf ^ 1) * ASZ) * 4;
            #pragma unroll
            for (int p = 0; p < 32; p++) {
                int rr = p * 4 + rS;
                int grow = tn * GBM + rr;
                if (grow >= n) grow = n - 1;
                cp_async4(dstb + (uint32_t)(kS * AST + rr) * 4,
                          &x_out[(size_t)grow * D + kS]);
            }
            asm volatile("cp.async.commit_group;");
            asm volatile("cp.async.wait_group 1;");
        } else {
            asm volatile("cp.async.wait_group 0;");
        }
        __syncthreads();           // current buffer visible to all

        const float* A = As + buf * ASZ;
        unsigned long long acc[16];
        #pragma unroll
        for (int j = 0; j < 16; j++) acc[j] = 0ull;

        #pragma unroll 8
        for (int kk = 0; kk < D; kk++) {
            float a0 = A[kk * AST + r0];
            float a1 = A[kk * AST + r0 + 64];
            unsigned long long aa0, aa1;
            asm("mov.b64 %0, {%1, %1};" : "=l"(aa0) : "r"(__float_as_uint(a0)));
            asm("mov.b64 %0, {%1, %1};" : "=l"(aa1) : "r"(__float_as_uint(a1)));
            const ulonglong2* wp = reinterpret_cast<const ulonglong2*>(&Ws[kk * D + cg * 16]);
            ulonglong2 u0 = wp[0];
            ulonglong2 u1 = wp[1];
            ulonglong2 u2 = wp[2];
            ulonglong2 u3 = wp[3];
            asm("fma.rn.f32x2 %0, %1, %2, %0;" : "+l"(acc[0])  : "l"(aa0), "l"(u0.x));
            asm("fma.rn.f32x2 %0, %1, %2, %0;" : "+l"(acc[1])  : "l"(aa0), "l"(u0.y));
            asm("fma.rn.f32x2 %0, %1, %2, %0;" : "+l"(acc[2])  : "l"(aa0), "l"(u1.x));
            asm("fma.rn.f32x2 %0, %1, %2, %0;" : "+l"(acc[3])  : "l"(aa0), "l"(u1.y));
            asm("fma.rn.f32x2 %0, %1, %2, %0;" : "+l"(acc[4])  : "l"(aa0), "l"(u2.x));
            asm("fma.rn.f32x2 %0, %1, %2, %0;" : "+l"(acc[5])  : "l"(aa0), "l"(u2.y));
            asm("fma.rn.f32x2 %0, %1, %2, %0;" : "+l"(acc[6])  : "l"(aa0), "l"(u3.x));
            asm("fma.rn.f32x2 %0, %1, %2, %0;" : "+l"(acc[7])  : "l"(aa0), "l"(u3.y));
            asm("fma.rn.f32x2 %0, %1, %2, %0;" : "+l"(acc[8])  : "l"(aa1), "l"(u0.x));
            asm("fma.rn.f32x2 %0, %1, %2, %0;" : "+l"(acc[9])  : "l"(aa1), "l"(u0.y));
            asm("fma.rn.f32x2 %0, %1, %2, %0;" : "+l"(acc[10]) : "l"(aa1), "l"(u1.x));
            asm("fma.rn.f32x2 %0, %1, %2, %0;" : "+l"(acc[11]) : "l"(aa1), "l"(u1.y));
            asm("fma.rn.f32x2 %0, %1, %2, %0;" : "+l"(acc[12]) : "l"(aa1), "l"(u2.x));
            asm("fma.rn.f32x2 %0, %1, %2, %0;" : "+l"(acc[13]) : "l"(aa1), "l"(u2.y));
            asm("fma.rn.f32x2 %0, %1, %2, %0;" : "+l"(acc[14]) : "l"(aa1), "l"(u3.x));
            asm("fma.rn.f32x2 %0, %1, %2, %0;" : "+l"(acc[15]) : "l"(aa1), "l"(u3.y));
        }

        int gr0 = t * GBM + r0;
        int gr1 = gr0 + 64;
        if (gr0 < n) {
            float* dst = g_y + (size_t)gr0 * D + cg * 16;
            stg_el32B(dst,     acc[0], acc[1], acc[2],  acc[3]);
            stg_el32B(dst + 8, acc[4], acc[5], acc[6],  acc[7]);
        }
        if (gr1 < n) {
            float* dst = g_y + (size_t)gr1 * D + cg * 16;
            stg_el32B(dst,     acc[8],  acc[9],  acc[10], acc[11]);
            stg_el32B(dst + 8, acc[12], acc[13], acc[14], acc[15]);
        }

        __syncthreads();           // compute done before buffer is restaged
        buf ^= 1;
    }
}

// ---------------------------------------------------------------------------
// dtype detection
// ---------------------------------------------------------------------------
__global__ void detect_dtype(const unsigned int* __restrict__ ei_raw, int nwords)
{
    __shared__ int bad;
    if (threadIdx.x == 0) bad = 0;
    __syncthreads();
    int limit = 1024;
    if (limit > nwords) limit = nwords & ~1;
    for (int i = threadIdx.x; i * 2 + 1 < limit; i += blockDim.x)
        if (ei_raw[i * 2 + 1] != 0u) atomicOr(&bad, 1);
    __syncthreads();
    if (threadIdx.x == 0) g_bad = bad;
}

// ---------------------------------------------------------------------------
// Edge kernel (unchanged from R6 — at L2 LTS cap):
// out[e] = sigmoid(dot(y[src], x_in[dst])), warp = 2 edges, 32B evict-last.
// ---------------------------------------------------------------------------
__global__ void __launch_bounds__(256) edge_bilinear(
    const float* __restrict__ x_in,
    const void* __restrict__ ei,
    float* __restrict__ out,
    int E)
{
    const unsigned int gthread = blockIdx.x * blockDim.x + threadIdx.x;
    const int warp_id = (int)(gthread >> 5);
    const int lane = threadIdx.x & 31;
    const int half = lane >> 4;
    const int sub  = lane & 15;
    const int e    = warp_id * 2 + half;
    if (e >= E) return;

    long long s, d;
    if (g_bad) {
        const int* p = (const int*)ei;
        s = __ldcs(&p[e]);
        d = __ldcs(&p[E + e]);
    } else {
        const long long* p = (const long long*)ei;
        s = __ldcs(&p[e]);
        d = __ldcs(&p[(long long)E + e]);
    }

    float4 a0, a1, b0, b1;
    ldg_el32B(g_y  + s * D + sub * 8, a0, a1);
    ldg_el32B(x_in + d * D + sub * 8, b0, b1);

    float v = a0.x * b0.x + a0.y * b0.y + a0.z * b0.z + a0.w * b0.w
            + a1.x * b1.x + a1.y * b1.y + a1.z * b1.z + a1.w * b1.w;

    #pragma unroll
    for (int o = 8; o > 0; o >>= 1)
        v += __shfl_xor_sync(0xFFFFFFFFu, v, o);

    if (sub == 0)
        __stcs(&out[e], 1.0f / (1.0f + __expf(-v)));
}

// ---------------------------------------------------------------------------
// Launch
// ---------------------------------------------------------------------------
#define GEMM_SMEM ((D * D + 2 * ASZ) * sizeof(float))

extern "C" void kernel_launch(void* const* d_in, const int* in_sizes, int n_in,
                              void* d_out, int out_size)
{
    int i_xin = 0, i_xout = 1, i_ei = 2, i_w = 3;

    if (n_in == 4) {
        int w_idx = -1, ei_idx = -1;
        for (int i = 0; i < 4; i++)
            if (in_sizes[i] == D * D) w_idx = i;
        int idx[3], c = 0;
        for (int i = 0; i < 4; i++) if (i != w_idx) idx[c++] = i;
        if (w_idx >= 0 && c == 3) {
            if (in_sizes[idx[0]] == in_sizes[idx[1]])      { i_xin = idx[0]; i_xout = idx[1]; ei_idx = idx[2]; }
            else if (in_sizes[idx[0]] == in_sizes[idx[2]]) { i_xin = idx[0]; i_xout = idx[2]; ei_idx = idx[1]; }
            else                                            { i_xin = idx[1]; i_xout = idx[2]; ei_idx = idx[0]; }
            i_w = w_idx; i_ei = ei_idx;
        }
    }

    const float* x_in  = (const float*)d_in[i_xin];
    const float* x_out = (const float*)d_in[i_xout];
    const void*  ei    = d_in[i_ei];
    const float* W     = (const float*)d_in[i_w];
    float*       out   = (float*)d_out;

    int n = in_sizes[i_xin] / D;
    if (n > MAX_NODES) n = MAX_NODES;
    int E = in_sizes[i_ei] / 2;

    static int smem_set = 0;
    if (!smem_set) {
        cudaFuncSetAttribute(gemm_xout_w, cudaFuncAttributeMaxDynamicSharedMemorySize,
                             (int)GEMM_SMEM);
        smem_set = 1;
    }

    gemm_xout_w<<<NSM, 512, GEMM_SMEM>>>(x_out, W, n);

    detect_dtype<<<1, 256>>>((const unsigned int*)ei, in_sizes[i_ei] * 2);

    {
        long long total_threads = ((long long)E + 1) / 2 * 32;
        int blocks = (int)((total_threads + 255) / 256);
        edge_bilinear<<<blocks, 256>>>(x_in, ei, out, E);
    }
}